// round 15
// baseline (speedup 1.0000x reference)
#include <cuda_runtime.h>
#include <math.h>
#include <stdint.h>

typedef unsigned long long ull;

#define Bz 32
#define Sz 512
#define Ez 256
#define Uz 1024
#define U2 2048
#define BSz (Bz*Sz)   // 16384

#define NBLK 128
#define NTHR 512

#define PITCH  1028            // floats per h/a row (pitch%32==4 -> bank-staggered)
#define PITCHB (PITCH*4)       // 4112 bytes
#define BULKB  (Bz*PITCHB)     // 131584 bytes staged per phase

// -------- scratch (device globals; no allocation allowed) --------
__device__ float g_Xg[(size_t)BSz * U2];
__device__ float g_Xc[(size_t)BSz * Uz];
__device__ float g_y0[(size_t)BSz * Uz];
__device__ float g_h [Bz * PITCH];
__device__ float g_a [Bz * PITCH];
__device__ float g_u [Bz * Uz];

// -------- monotonic grid barrier (R8 design — empirically best) --------
__device__ unsigned g_ctr  = 0;
__device__ unsigned g_base = 0;

__global__ void set_base() { g_base = g_ctr; }

__device__ __forceinline__ void gsync(unsigned tgt) {
    __syncthreads();
    if (threadIdx.x == 0) {
        unsigned old;
        asm volatile("atom.add.release.gpu.global.u32 %0, [%1], 1;"
                     : "=r"(old) : "l"(&g_ctr) : "memory");
        unsigned v;
        for (;;) {
            asm volatile("ld.acquire.gpu.global.u32 %0, [%1];"
                         : "=r"(v) : "l"(&g_ctr) : "memory");
            if ((int)(v - tgt) >= 0) break;
            __nanosleep(40);
        }
    }
    __syncthreads();
}

// -------- f32x2 helpers --------
__device__ __forceinline__ void fma2(ull& d, ull a, ull b) {
    asm("fma.rn.f32x2 %0, %1, %2, %0;" : "+l"(d) : "l"(a), "l"(b));
}
__device__ __forceinline__ void add2(ull& d, ull a) {
    asm("add.rn.f32x2 %0, %1, %0;" : "+l"(d) : "l"(a));
}
__device__ __forceinline__ float hadd2(ull v) {
    float2 r; asm("mov.b64 {%0,%1}, %2;" : "=f"(r.x), "=f"(r.y) : "l"(v));
    return r.x + r.y;
}

// -------- mbarrier / bulk-async helpers --------
__device__ __forceinline__ void mbar_init(uint32_t mbar) {
    asm volatile("mbarrier.init.shared.b64 [%0], %1;" :: "r"(mbar), "r"(1) : "memory");
}
__device__ __forceinline__ void mbar_expect(uint32_t mbar, uint32_t bytes) {
    asm volatile("mbarrier.arrive.expect_tx.shared.b64 _, [%0], %1;"
                 :: "r"(mbar), "r"(bytes) : "memory");
}
__device__ __forceinline__ void bulk_g2s(uint32_t dst, const void* src,
                                         uint32_t bytes, uint32_t mbar) {
    asm volatile("cp.async.bulk.shared::cta.global.mbarrier::complete_tx::bytes "
                 "[%0], [%1], %2, [%3];"
                 :: "r"(dst), "l"(src), "r"(bytes), "r"(mbar) : "memory");
}
__device__ __forceinline__ void mbar_wait(uint32_t mbar, uint32_t parity) {
    asm volatile(
        "{\n\t.reg .pred P;\n"
        "W_%=:\n\t"
        "mbarrier.try_wait.parity.acquire.cta.shared::cta.b64 P, [%0], %1, 0x989680;\n\t"
        "@P bra D_%=;\n\t"
        "bra W_%=;\n"
        "D_%=:\n\t}"
        :: "r"(mbar), "r"(parity) : "memory");
}
__device__ __forceinline__ void fence_async() {
    asm volatile("fence.proxy.async;" ::: "memory");
}

// ------------------------------------------------------------------
// C[M,N] = A @ W + bias — FFMA2 GEMM with broadcast-friendly lane map.
// 512 threads, block tile 128x128, warp grid 4x4 (warp tile 32x32).
// Lane: lr = lane>>3 (row group), lc = lane&7 (col group).
// Thread tile: 8 rows (lr+4i) x 4 cols (lc+8j), k-packed f32x2 accumulators.
// A-loads: 4 distinct rows/warp, stride 20 floats -> offsets {0,20,8,28} mod 32
// -> disjoint bank quads, 1 crossbar cyc. W-loads: 8 distinct cols cover all
// 32 banks, 1 cyc. Inner loop is FFMA2-pipe-bound (84% FMA density).
#define GLD 20   // SMEM row stride in floats

__global__ __launch_bounds__(512) void sgemm_bias(
    const float* __restrict__ Abase, const int* __restrict__ xidx,
    const float* __restrict__ W, const float* __restrict__ bias,
    float* __restrict__ C, int M, int N, int K)
{
    __shared__ float As[128 * GLD];   // [row][k0..15]
    __shared__ float Ws[128 * GLD];   // [col][k0..15] (transposed)

    const int tid  = threadIdx.x;
    const int warp = tid >> 5;
    const int lane = tid & 31;
    const int lr   = lane >> 3;       // 0..3
    const int lc   = lane & 7;        // 0..7
    const int wm   = warp >> 2;       // 0..3
    const int wn   = warp & 3;        // 0..3
    const int rowBase = blockIdx.y * 128;
    const int colBase = blockIdx.x * 128;
    const int wrow = wm * 32;
    const int wcol = wn * 32;

    // A staging: row = tid>>2, k-quad = (tid&3)*4
    const int sar = tid >> 2;
    const int sak = (tid & 3) * 4;
    const float* arowptr = xidx ? Abase + (size_t)xidx[rowBase + sar] * K
                                : Abase + (size_t)(rowBase + sar) * K;
    // W staging (transpose): n = tid>>2, k-quad = (tid&3)*4
    const int swn = tid >> 2;
    const int swk = (tid & 3) * 4;

    ull acc[8][4];
#pragma unroll
    for (int i = 0; i < 8; i++)
#pragma unroll
        for (int j = 0; j < 4; j++) acc[i][j] = 0ULL;

    for (int k0 = 0; k0 < K; k0 += 16) {
        // ---- stage A (128x16) ----
        *(float4*)&As[sar * GLD + sak] = *(const float4*)&arowptr[k0 + sak];
        // ---- stage W transposed (16x128 -> [n][k]) ----
        {
            const float* wp = W + (size_t)(k0 + swk) * N + colBase + swn;
            float w0 = wp[0];
            float w1 = wp[(size_t)N];
            float w2 = wp[(size_t)2 * N];
            float w3 = wp[(size_t)3 * N];
            *(float4*)&Ws[swn * GLD + swk] = make_float4(w0, w1, w2, w3);
        }
        __syncthreads();

#pragma unroll
        for (int ps = 0; ps < 4; ps++) {          // 4 k per step (2 f32x2 pairs)
            ulonglong2 a[8];
#pragma unroll
            for (int i = 0; i < 8; i++)
                a[i] = *(const ulonglong2*)&As[(wrow + lr + 4 * i) * GLD + ps * 4];
#pragma unroll
            for (int j = 0; j < 4; j++) {
                ulonglong2 w = *(const ulonglong2*)&Ws[(wcol + lc + 8 * j) * GLD + ps * 4];
#pragma unroll
                for (int i = 0; i < 8; i++) {
                    fma2(acc[i][j], a[i].x, w.x);
                    fma2(acc[i][j], a[i].y, w.y);
                }
            }
        }
        __syncthreads();
    }

    // ---- epilogue: horizontal add + bias ----
#pragma unroll
    for (int j = 0; j < 4; j++) {
        int col = colBase + wcol + lc + 8 * j;
        float bj = bias[col];
#pragma unroll
        for (int i = 0; i < 8; i++) {
            int row = rowBase + wrow + lr + 4 * i;
            C[(size_t)row * N + col] = hadd2(acc[i][j]) + bj;
        }
    }
}

// ------------------------------------------------------------------
// Persistent GRU scan — byte-exact round-8 version (best measured).
#define SWG_BYTES 65664
#define SWC_BYTES 32896
#define SH_OFF    (SWG_BYTES + SWC_BYTES)        // 98560
#define MBAR_OFF  (SH_OFF + BULKB)               // 230144
#define SMEM_BYTES (MBAR_OFF + 16)               // 230160

__global__ __launch_bounds__(NTHR) void gru_scan(
    const float* __restrict__ Wgh,   // [1024][2048]
    const float* __restrict__ Wch,   // [1024][1024]
    const float* __restrict__ Xg,    // [16384][2048]
    const float* __restrict__ Xc,    // [16384][1024]
    const float* __restrict__ h0,
    float* __restrict__ y,
    float* __restrict__ s_out)
{
    extern __shared__ char smraw[];
    char*  swg = smraw;
    char*  swc = smraw + SWG_BYTES;
    float* sh  = (float*)(smraw + SH_OFF);
    ull*   sred = (ull*)sh;

    const int tid = threadIdx.x;
    const int blk = blockIdx.x;
    const int jg0 = blk * 16;
    const int jc0 = blk * 8;
    const bool is_r = (jg0 < Uz);

    const uint32_t sh_s  = (uint32_t)__cvta_generic_to_shared(sh);
    const uint32_t mbar  = (uint32_t)__cvta_generic_to_shared(smraw + MBAR_OFF);

    const int k8 = tid >> 6;
    const int bg1 = (tid >> 3) & 7;
    const int jj1 = tid & 7;
    const int kc = tid >> 5;
    const int bg2 = (tid >> 2) & 7;
    const int jj2 = tid & 3;
    const int e1b = tid >> 4, e1j = tid & 15;
    const int e2b = tid >> 3, e2j = tid & 7;

    unsigned base = 0, nb = 0;
    if (tid == 0) base = g_base;

    if (tid == 0) mbar_init(mbar);
    unsigned parity = 0;

    // ---- preload W slices, transposed (once per layer) ----
    for (int i = tid; i < 4096; i += NTHR) {
        int k = i >> 2, c4 = (i & 3) * 4;
        float4 v = *(const float4*)&Wgh[(size_t)k * U2 + jg0 + c4];
        float vv[4] = {v.x, v.y, v.z, v.w};
#pragma unroll
        for (int d = 0; d < 4; d++) {
            int c = c4 + d;
            *(float*)(swg + (c >> 1) * 8208 + (c & 1) * 4096 + k * 4) = vv[d];
        }
    }
    for (int i = tid; i < 2048; i += NTHR) {
        int k = i >> 1, cb = (i & 1) * 4;
        float4 v = *(const float4*)&Wch[(size_t)k * Uz + jc0 + cb];
        float vv[4] = {v.x, v.y, v.z, v.w};
#pragma unroll
        for (int d = 0; d < 4; d++)
            *(float*)(swc + (cb + d) * 4112 + k * 4) = vv[d];
    }
    for (int i = blk * NTHR + tid; i < Bz * Uz; i += NBLK * NTHR) {
        int b = i >> 10, u = i & 1023;
        __stcg(&g_h[b * PITCH + u], h0[i]);
    }
    nb++; gsync(base + nb * NBLK);

    for (int t = 0; t < Sz; t++) {
        // ================= phase 1: gates =================
        if (tid == 0) {
            fence_async();
            mbar_expect(mbar, BULKB);
            bulk_g2s(sh_s, g_h, BULKB, mbar);
        }
        int m1 = e1b * Sz + t;
        float xg_pf = __ldcg(&Xg[(size_t)m1 * U2 + jg0 + e1j]);
        float h_pf = 0.f;
        if (is_r) h_pf = __ldcg(&g_h[e1b * PITCH + jg0 + e1j]);

        mbar_wait(mbar, parity); parity ^= 1;

        ull a00 = 0, a01 = 0, a10 = 0, a11 = 0, a20 = 0, a21 = 0, a30 = 0, a31 = 0;
        {
            const ulonglong2* h0p = (const ulonglong2*)(sh + (bg1 +  0) * PITCH + k8 * 128);
            const ulonglong2* h1p = (const ulonglong2*)(sh + (bg1 +  8) * PITCH + k8 * 128);
            const ulonglong2* h2p = (const ulonglong2*)(sh + (bg1 + 16) * PITCH + k8 * 128);
            const ulonglong2* h3p = (const ulonglong2*)(sh + (bg1 + 24) * PITCH + k8 * 128);
            const ulonglong2* w0p = (const ulonglong2*)(swg + jj1 * 8208 + k8 * 512);
            const ulonglong2* w1p = (const ulonglong2*)(swg + jj1 * 8208 + 4096 + k8 * 512);
#pragma unroll 4
            for (int i = 0; i < 32; i++) {
                ulonglong2 w0 = w0p[i], w1 = w1p[i];
                ulonglong2 hv;
                hv = h0p[i];
                fma2(a00, hv.x, w0.x); fma2(a00, hv.y, w0.y);
                fma2(a01, hv.x, w1.x); fma2(a01, hv.y, w1.y);
                hv = h1p[i];
                fma2(a10, hv.x, w0.x); fma2(a10, hv.y, w0.y);
                fma2(a11, hv.x, w1.x); fma2(a11, hv.y, w1.y);
                hv = h2p[i];
                fma2(a20, hv.x, w0.x); fma2(a20, hv.y, w0.y);
                fma2(a21, hv.x, w1.x); fma2(a21, hv.y, w1.y);
                hv = h3p[i];
                fma2(a30, hv.x, w0.x); fma2(a30, hv.y, w0.y);
                fma2(a31, hv.x, w1.x); fma2(a31, hv.y, w1.y);
            }
        }
        __syncthreads();
        {
            int ib = k8 * 512 + jj1 * 2;
            *(ulonglong2*)&sred[ib + (bg1 +  0) * 16] = make_ulonglong2(a00, a01);
            *(ulonglong2*)&sred[ib + (bg1 +  8) * 16] = make_ulonglong2(a10, a11);
            *(ulonglong2*)&sred[ib + (bg1 + 16) * 16] = make_ulonglong2(a20, a21);
            *(ulonglong2*)&sred[ib + (bg1 + 24) * 16] = make_ulonglong2(a30, a31);
        }
        __syncthreads();
        {
            ull s = sred[tid];
#pragma unroll
            for (int p = 1; p < 8; p++) add2(s, sred[p * 512 + tid]);
            float v = 1.f / (1.f + expf(-(xg_pf + hadd2(s))));
            if (is_r) __stcg(&g_a[e1b * PITCH + jg0 + e1j], v * h_pf);
            else      __stcg(&g_u[e1b * Uz + jg0 - Uz + e1j], v);
        }
        nb++; gsync(base + nb * NBLK);

        // ================= phase 2: candidate + update =================
        if (tid == 0) {
            fence_async();
            mbar_expect(mbar, BULKB);
            bulk_g2s(sh_s, g_a, BULKB, mbar);
        }
        int m2 = e2b * Sz + t;
        float xc_pf = 0.f, u_pf = 0.f, ho_pf = 0.f;
        if (tid < 256) {
            xc_pf = __ldcg(&Xc[(size_t)m2 * Uz + jc0 + e2j]);
            u_pf  = __ldcg(&g_u[e2b * Uz + jc0 + e2j]);
            ho_pf = __ldcg(&g_h[e2b * PITCH + jc0 + e2j]);
        }

        mbar_wait(mbar, parity); parity ^= 1;

        ull c00 = 0, c01 = 0, c10 = 0, c11 = 0, c20 = 0, c21 = 0, c30 = 0, c31 = 0;
        {
            const ulonglong2* a0p = (const ulonglong2*)(sh + (bg2 +  0) * PITCH + kc * 64);
            const ulonglong2* a1p = (const ulonglong2*)(sh + (bg2 +  8) * PITCH + kc * 64);
            const ulonglong2* a2p = (const ulonglong2*)(sh + (bg2 + 16) * PITCH + kc * 64);
            const ulonglong2* a3p = (const ulonglong2*)(sh + (bg2 + 24) * PITCH + kc * 64);
            const ulonglong2* wAp = (const ulonglong2*)(swc + (jj2 * 2) * 4112 + kc * 256);
            const ulonglong2* wBp = (const ulonglong2*)(swc + (jj2 * 2 + 1) * 4112 + kc * 256);
#pragma unroll 4
            for (int i = 0; i < 16; i++) {
                ulonglong2 wA = wAp[i], wB = wBp[i];
                ulonglong2 av;
                av = a0p[i];
                fma2(c00, av.x, wA.x); fma2(c00, av.y, wA.y);
                fma2(c01, av.x, wB.x); fma2(c01, av.y, wB.y);
                av = a1p[i];
                fma2(c10, av.x, wA.x); fma2(c10, av.y, wA.y);
                fma2(c11, av.x, wB.x); fma2(c11, av.y, wB.y);
                av = a2p[i];
                fma2(c20, av.x, wA.x); fma2(c20, av.y, wA.y);
                fma2(c21, av.x, wB.x); fma2(c21, av.y, wB.y);
                av = a3p[i];
                fma2(c30, av.x, wA.x); fma2(c30, av.y, wA.y);
                fma2(c31, av.x, wB.x); fma2(c31, av.y, wB.y);
            }
        }
        __syncthreads();
        {
            int ib = kc * 256 + jj2 * 2;
            *(ulonglong2*)&sred[ib + (bg2 +  0) * 8] = make_ulonglong2(c00, c01);
            *(ulonglong2*)&sred[ib + (bg2 +  8) * 8] = make_ulonglong2(c10, c11);
            *(ulonglong2*)&sred[ib + (bg2 + 16) * 8] = make_ulonglong2(c20, c21);
            *(ulonglong2*)&sred[ib + (bg2 + 24) * 8] = make_ulonglong2(c30, c31);
        }
        __syncthreads();
        if (tid < 256) {
            ull s = sred[tid];
#pragma unroll
            for (int p = 1; p < 16; p++) add2(s, sred[p * 256 + tid]);
            float c  = tanhf(xc_pf + hadd2(s));
            float hn = u_pf * ho_pf + (1.f - u_pf) * c;
            __stcg(&g_h[e2b * PITCH + jc0 + e2j], hn);
            y[(size_t)m2 * Uz + jc0 + e2j] = hn;
        }
        nb++; gsync(base + nb * NBLK);
    }

    for (int i = blk * NTHR + tid; i < Bz * Uz; i += NBLK * NTHR) {
        int b = i >> 10, u = i & 1023;
        s_out[i] = __ldcg(&g_h[b * PITCH + u]);
    }
}

// ------------------------------------------------------------------
extern "C" void kernel_launch(void* const* d_in, const int* in_sizes, int n_in,
                              void* d_out, int out_size)
{
    const int*   x    = (const int*)  d_in[0];
    const float* h0_0 = (const float*)d_in[1];
    const float* h0_1 = (const float*)d_in[2];
    const float* emb  = (const float*)d_in[3];
    const float* Wg0  = (const float*)d_in[4];
    const float* bg0  = (const float*)d_in[5];
    const float* Wc0  = (const float*)d_in[6];
    const float* bc0  = (const float*)d_in[7];
    const float* Wg1  = (const float*)d_in[8];
    const float* bg1  = (const float*)d_in[9];
    const float* Wc1  = (const float*)d_in[10];
    const float* bc1  = (const float*)d_in[11];
    float* out = (float*)d_out;

    float *Xg, *Xc, *y0;
    cudaGetSymbolAddress((void**)&Xg, g_Xg);
    cudaGetSymbolAddress((void**)&Xc, g_Xc);
    cudaGetSymbolAddress((void**)&y0, g_y0);

    static int smem_set = 0;
    if (!smem_set) {
        cudaFuncSetAttribute(gru_scan, cudaFuncAttributeMaxDynamicSharedMemorySize, SMEM_BYTES);
        smem_set = 1;
    }

    float* s0_out = out + (size_t)BSz * Uz;
    float* s1_out = s0_out + Bz * Uz;

    // ---------- layer 0 ----------
    sgemm_bias<<<dim3(U2 / 128, BSz / 128), 512>>>(emb, x, Wg0, bg0, Xg, BSz, U2, Ez);
    sgemm_bias<<<dim3(Uz / 128, BSz / 128), 512>>>(emb, x, Wc0, bc0, Xc, BSz, Uz, Ez);
    set_base<<<1, 1>>>();
    gru_scan<<<NBLK, NTHR, SMEM_BYTES>>>(
        Wg0 + (size_t)Ez * U2, Wc0 + (size_t)Ez * Uz, Xg, Xc, h0_0, y0, s0_out);

    // ---------- layer 1 ----------
    sgemm_bias<<<dim3(U2 / 128, BSz / 128), 512>>>(y0, nullptr, Wg1, bg1, Xg, BSz, U2, Uz);
    sgemm_bias<<<dim3(Uz / 128, BSz / 128), 512>>>(y0, nullptr, Wc1, bc1, Xc, BSz, Uz, Uz);
    set_base<<<1, 1>>>();
    gru_scan<<<NBLK, NTHR, SMEM_BYTES>>>(
        Wg1 + (size_t)Uz * U2, Wc1 + (size_t)Uz * Uz, Xg, Xc, h0_1, out, s1_out);
}

// round 16
// speedup vs baseline: 1.0695x; 1.0695x over previous
#include <cuda_runtime.h>
#include <math.h>
#include <stdint.h>

typedef unsigned long long ull;

#define Bz 32
#define Sz 512
#define Ez 256
#define Uz 1024
#define U2 2048
#define BSz (Bz*Sz)   // 16384

#define NBLK 128
#define NTHR 512

#define PITCH  1028            // floats per h/a row (pitch%32==4 -> bank-staggered)
#define PITCHB (PITCH*4)       // 4112 bytes
#define BULKB  (Bz*PITCHB)     // 131584 bytes staged per phase

// -------- scratch (device globals; no allocation allowed) --------
__device__ float g_Xg[(size_t)BSz * U2];
__device__ float g_Xc[(size_t)BSz * Uz];
__device__ float g_y0[(size_t)BSz * Uz];
__device__ float g_h [Bz * PITCH];
__device__ float g_a [Bz * PITCH];
__device__ float g_u [Bz * Uz];

// -------- monotonic grid barrier (R8 design — empirically best) --------
__device__ unsigned g_ctr  = 0;
__device__ unsigned g_base = 0;

__global__ void set_base() { g_base = g_ctr; }

__device__ __forceinline__ void gsync(unsigned tgt) {
    __syncthreads();
    if (threadIdx.x == 0) {
        unsigned old;
        asm volatile("atom.add.release.gpu.global.u32 %0, [%1], 1;"
                     : "=r"(old) : "l"(&g_ctr) : "memory");
        unsigned v;
        for (;;) {
            asm volatile("ld.acquire.gpu.global.u32 %0, [%1];"
                         : "=r"(v) : "l"(&g_ctr) : "memory");
            if ((int)(v - tgt) >= 0) break;
            __nanosleep(40);
        }
    }
    __syncthreads();
}

// -------- f32x2 helpers --------
__device__ __forceinline__ void fma2(ull& d, ull a, ull b) {
    asm("fma.rn.f32x2 %0, %1, %2, %0;" : "+l"(d) : "l"(a), "l"(b));
}
__device__ __forceinline__ void add2(ull& d, ull a) {
    asm("add.rn.f32x2 %0, %1, %0;" : "+l"(d) : "l"(a));
}
__device__ __forceinline__ float hadd2(ull v) {
    float2 r; asm("mov.b64 {%0,%1}, %2;" : "=f"(r.x), "=f"(r.y) : "l"(v));
    return r.x + r.y;
}
__device__ __forceinline__ float2 unpack2(ull v) {
    float2 r; asm("mov.b64 {%0,%1}, %2;" : "=f"(r.x), "=f"(r.y) : "l"(v));
    return r;
}
__device__ __forceinline__ ull dup1(float x) {
    ull r; asm("mov.b64 %0, {%1,%1};" : "=l"(r) : "f"(x)); return r;
}

// -------- mbarrier / bulk-async helpers --------
__device__ __forceinline__ void mbar_init(uint32_t mbar) {
    asm volatile("mbarrier.init.shared.b64 [%0], %1;" :: "r"(mbar), "r"(1) : "memory");
}
__device__ __forceinline__ void mbar_expect(uint32_t mbar, uint32_t bytes) {
    asm volatile("mbarrier.arrive.expect_tx.shared.b64 _, [%0], %1;"
                 :: "r"(mbar), "r"(bytes) : "memory");
}
__device__ __forceinline__ void bulk_g2s(uint32_t dst, const void* src,
                                         uint32_t bytes, uint32_t mbar) {
    asm volatile("cp.async.bulk.shared::cta.global.mbarrier::complete_tx::bytes "
                 "[%0], [%1], %2, [%3];"
                 :: "r"(dst), "l"(src), "r"(bytes), "r"(mbar) : "memory");
}
__device__ __forceinline__ void mbar_wait(uint32_t mbar, uint32_t parity) {
    asm volatile(
        "{\n\t.reg .pred P;\n"
        "W_%=:\n\t"
        "mbarrier.try_wait.parity.acquire.cta.shared::cta.b64 P, [%0], %1, 0x989680;\n\t"
        "@P bra D_%=;\n\t"
        "bra W_%=;\n"
        "D_%=:\n\t}"
        :: "r"(mbar), "r"(parity) : "memory");
}
__device__ __forceinline__ void fence_async() {
    asm volatile("fence.proxy.async;" ::: "memory");
}

// ------------------------------------------------------------------
// C[M,N] = A @ W + bias — N-packed FFMA2 GEMM, in-register A-dup.
// R2's exact staging/tiles (256 thr, 128x128 block, 8x8 thread tile),
// but accumulators are f32x2 pairs along N: acc[i][j] covers cols 2j,2j+1.
// Inner loop per kk: 4 LDS.128 + 8 mov.b64 (dup) + 32 fma2 = 44 issues/64 FMA.
// acc = 32 ull = 64 regs (same as scalar) -> 2 blocks/SM preserved.
__global__ __launch_bounds__(256, 2) void sgemm_bias(
    const float* __restrict__ Abase, const int* __restrict__ xidx,
    const float* __restrict__ W, const float* __restrict__ bias,
    float* __restrict__ C, int M, int N, int K)
{
    __shared__ float As[8][132];
    __shared__ float Bs[8][128];

    int tid = threadIdx.x;
    int ty = tid >> 4;
    int tx = tid & 15;
    int rowBase = blockIdx.y * 128;
    int colBase = blockIdx.x * 128;

    int arow  = tid >> 1;
    int acol4 = (tid & 1) * 4;
    int am = rowBase + arow;
    const float* arowptr;
    if (xidx) arowptr = Abase + (size_t)xidx[am] * K;
    else      arowptr = Abase + (size_t)am * K;

    int brow  = tid >> 5;
    int bcol4 = (tid & 31) * 4;

    ull acc[8][4];
#pragma unroll
    for (int i = 0; i < 8; i++)
#pragma unroll
        for (int j = 0; j < 4; j++) acc[i][j] = 0ULL;

    for (int k0 = 0; k0 < K; k0 += 8) {
        float4 av = *(const float4*)&arowptr[k0 + acol4];
        As[acol4 + 0][arow] = av.x;
        As[acol4 + 1][arow] = av.y;
        As[acol4 + 2][arow] = av.z;
        As[acol4 + 3][arow] = av.w;

        float4 bv = *(const float4*)&W[(size_t)(k0 + brow) * N + colBase + bcol4];
        *(float4*)&Bs[brow][bcol4] = bv;

        __syncthreads();
#pragma unroll
        for (int kk = 0; kk < 8; kk++) {
            float4 a0 = *(const float4*)&As[kk][ty * 8];
            float4 a1 = *(const float4*)&As[kk][ty * 8 + 4];
            ulonglong2 b01 = *(const ulonglong2*)&Bs[kk][tx * 8];
            ulonglong2 b23 = *(const ulonglong2*)&Bs[kk][tx * 8 + 4];
            ull ar[8];
            ar[0] = dup1(a0.x); ar[1] = dup1(a0.y);
            ar[2] = dup1(a0.z); ar[3] = dup1(a0.w);
            ar[4] = dup1(a1.x); ar[5] = dup1(a1.y);
            ar[6] = dup1(a1.z); ar[7] = dup1(a1.w);
#pragma unroll
            for (int i = 0; i < 8; i++) {
                fma2(acc[i][0], ar[i], b01.x);
                fma2(acc[i][1], ar[i], b01.y);
                fma2(acc[i][2], ar[i], b23.x);
                fma2(acc[i][3], ar[i], b23.y);
            }
        }
        __syncthreads();
    }

    int col0 = colBase + tx * 8;
    float4 bia0 = *(const float4*)&bias[col0];
    float4 bia1 = *(const float4*)&bias[col0 + 4];
#pragma unroll
    for (int i = 0; i < 8; i++) {
        int row = rowBase + ty * 8 + i;
        float2 f0 = unpack2(acc[i][0]);
        float2 f1 = unpack2(acc[i][1]);
        float2 f2 = unpack2(acc[i][2]);
        float2 f3 = unpack2(acc[i][3]);
        float4 v0 = make_float4(f0.x + bia0.x, f0.y + bia0.y,
                                f1.x + bia0.z, f1.y + bia0.w);
        float4 v1 = make_float4(f2.x + bia1.x, f2.y + bia1.y,
                                f3.x + bia1.z, f3.y + bia1.w);
        *(float4*)&C[(size_t)row * N + col0]     = v0;
        *(float4*)&C[(size_t)row * N + col0 + 4] = v1;
    }
}

// ------------------------------------------------------------------
// Persistent GRU scan — byte-exact round-8 version (best measured).
#define SWG_BYTES 65664
#define SWC_BYTES 32896
#define SH_OFF    (SWG_BYTES + SWC_BYTES)        // 98560
#define MBAR_OFF  (SH_OFF + BULKB)               // 230144
#define SMEM_BYTES (MBAR_OFF + 16)               // 230160

__global__ __launch_bounds__(NTHR) void gru_scan(
    const float* __restrict__ Wgh,   // [1024][2048]
    const float* __restrict__ Wch,   // [1024][1024]
    const float* __restrict__ Xg,    // [16384][2048]
    const float* __restrict__ Xc,    // [16384][1024]
    const float* __restrict__ h0,
    float* __restrict__ y,
    float* __restrict__ s_out)
{
    extern __shared__ char smraw[];
    char*  swg = smraw;
    char*  swc = smraw + SWG_BYTES;
    float* sh  = (float*)(smraw + SH_OFF);
    ull*   sred = (ull*)sh;

    const int tid = threadIdx.x;
    const int blk = blockIdx.x;
    const int jg0 = blk * 16;
    const int jc0 = blk * 8;
    const bool is_r = (jg0 < Uz);

    const uint32_t sh_s  = (uint32_t)__cvta_generic_to_shared(sh);
    const uint32_t mbar  = (uint32_t)__cvta_generic_to_shared(smraw + MBAR_OFF);

    const int k8 = tid >> 6;
    const int bg1 = (tid >> 3) & 7;
    const int jj1 = tid & 7;
    const int kc = tid >> 5;
    const int bg2 = (tid >> 2) & 7;
    const int jj2 = tid & 3;
    const int e1b = tid >> 4, e1j = tid & 15;
    const int e2b = tid >> 3, e2j = tid & 7;

    unsigned base = 0, nb = 0;
    if (tid == 0) base = g_base;

    if (tid == 0) mbar_init(mbar);
    unsigned parity = 0;

    // ---- preload W slices, transposed (once per layer) ----
    for (int i = tid; i < 4096; i += NTHR) {
        int k = i >> 2, c4 = (i & 3) * 4;
        float4 v = *(const float4*)&Wgh[(size_t)k * U2 + jg0 + c4];
        float vv[4] = {v.x, v.y, v.z, v.w};
#pragma unroll
        for (int d = 0; d < 4; d++) {
            int c = c4 + d;
            *(float*)(swg + (c >> 1) * 8208 + (c & 1) * 4096 + k * 4) = vv[d];
        }
    }
    for (int i = tid; i < 2048; i += NTHR) {
        int k = i >> 1, cb = (i & 1) * 4;
        float4 v = *(const float4*)&Wch[(size_t)k * Uz + jc0 + cb];
        float vv[4] = {v.x, v.y, v.z, v.w};
#pragma unroll
        for (int d = 0; d < 4; d++)
            *(float*)(swc + (cb + d) * 4112 + k * 4) = vv[d];
    }
    for (int i = blk * NTHR + tid; i < Bz * Uz; i += NBLK * NTHR) {
        int b = i >> 10, u = i & 1023;
        __stcg(&g_h[b * PITCH + u], h0[i]);
    }
    nb++; gsync(base + nb * NBLK);

    for (int t = 0; t < Sz; t++) {
        // ================= phase 1: gates =================
        if (tid == 0) {
            fence_async();
            mbar_expect(mbar, BULKB);
            bulk_g2s(sh_s, g_h, BULKB, mbar);
        }
        int m1 = e1b * Sz + t;
        float xg_pf = __ldcg(&Xg[(size_t)m1 * U2 + jg0 + e1j]);
        float h_pf = 0.f;
        if (is_r) h_pf = __ldcg(&g_h[e1b * PITCH + jg0 + e1j]);

        mbar_wait(mbar, parity); parity ^= 1;

        ull a00 = 0, a01 = 0, a10 = 0, a11 = 0, a20 = 0, a21 = 0, a30 = 0, a31 = 0;
        {
            const ulonglong2* h0p = (const ulonglong2*)(sh + (bg1 +  0) * PITCH + k8 * 128);
            const ulonglong2* h1p = (const ulonglong2*)(sh + (bg1 +  8) * PITCH + k8 * 128);
            const ulonglong2* h2p = (const ulonglong2*)(sh + (bg1 + 16) * PITCH + k8 * 128);
            const ulonglong2* h3p = (const ulonglong2*)(sh + (bg1 + 24) * PITCH + k8 * 128);
            const ulonglong2* w0p = (const ulonglong2*)(swg + jj1 * 8208 + k8 * 512);
            const ulonglong2* w1p = (const ulonglong2*)(swg + jj1 * 8208 + 4096 + k8 * 512);
#pragma unroll 4
            for (int i = 0; i < 32; i++) {
                ulonglong2 w0 = w0p[i], w1 = w1p[i];
                ulonglong2 hv;
                hv = h0p[i];
                fma2(a00, hv.x, w0.x); fma2(a00, hv.y, w0.y);
                fma2(a01, hv.x, w1.x); fma2(a01, hv.y, w1.y);
                hv = h1p[i];
                fma2(a10, hv.x, w0.x); fma2(a10, hv.y, w0.y);
                fma2(a11, hv.x, w1.x); fma2(a11, hv.y, w1.y);
                hv = h2p[i];
                fma2(a20, hv.x, w0.x); fma2(a20, hv.y, w0.y);
                fma2(a21, hv.x, w1.x); fma2(a21, hv.y, w1.y);
                hv = h3p[i];
                fma2(a30, hv.x, w0.x); fma2(a30, hv.y, w0.y);
                fma2(a31, hv.x, w1.x); fma2(a31, hv.y, w1.y);
            }
        }
        __syncthreads();
        {
            int ib = k8 * 512 + jj1 * 2;
            *(ulonglong2*)&sred[ib + (bg1 +  0) * 16] = make_ulonglong2(a00, a01);
            *(ulonglong2*)&sred[ib + (bg1 +  8) * 16] = make_ulonglong2(a10, a11);
            *(ulonglong2*)&sred[ib + (bg1 + 16) * 16] = make_ulonglong2(a20, a21);
            *(ulonglong2*)&sred[ib + (bg1 + 24) * 16] = make_ulonglong2(a30, a31);
        }
        __syncthreads();
        {
            ull s = sred[tid];
#pragma unroll
            for (int p = 1; p < 8; p++) add2(s, sred[p * 512 + tid]);
            float v = 1.f / (1.f + expf(-(xg_pf + hadd2(s))));
            if (is_r) __stcg(&g_a[e1b * PITCH + jg0 + e1j], v * h_pf);
            else      __stcg(&g_u[e1b * Uz + jg0 - Uz + e1j], v);
        }
        nb++; gsync(base + nb * NBLK);

        // ================= phase 2: candidate + update =================
        if (tid == 0) {
            fence_async();
            mbar_expect(mbar, BULKB);
            bulk_g2s(sh_s, g_a, BULKB, mbar);
        }
        int m2 = e2b * Sz + t;
        float xc_pf = 0.f, u_pf = 0.f, ho_pf = 0.f;
        if (tid < 256) {
            xc_pf = __ldcg(&Xc[(size_t)m2 * Uz + jc0 + e2j]);
            u_pf  = __ldcg(&g_u[e2b * Uz + jc0 + e2j]);
            ho_pf = __ldcg(&g_h[e2b * PITCH + jc0 + e2j]);
        }

        mbar_wait(mbar, parity); parity ^= 1;

        ull c00 = 0, c01 = 0, c10 = 0, c11 = 0, c20 = 0, c21 = 0, c30 = 0, c31 = 0;
        {
            const ulonglong2* a0p = (const ulonglong2*)(sh + (bg2 +  0) * PITCH + kc * 64);
            const ulonglong2* a1p = (const ulonglong2*)(sh + (bg2 +  8) * PITCH + kc * 64);
            const ulonglong2* a2p = (const ulonglong2*)(sh + (bg2 + 16) * PITCH + kc * 64);
            const ulonglong2* a3p = (const ulonglong2*)(sh + (bg2 + 24) * PITCH + kc * 64);
            const ulonglong2* wAp = (const ulonglong2*)(swc + (jj2 * 2) * 4112 + kc * 256);
            const ulonglong2* wBp = (const ulonglong2*)(swc + (jj2 * 2 + 1) * 4112 + kc * 256);
#pragma unroll 4
            for (int i = 0; i < 16; i++) {
                ulonglong2 wA = wAp[i], wB = wBp[i];
                ulonglong2 av;
                av = a0p[i];
                fma2(c00, av.x, wA.x); fma2(c00, av.y, wA.y);
                fma2(c01, av.x, wB.x); fma2(c01, av.y, wB.y);
                av = a1p[i];
                fma2(c10, av.x, wA.x); fma2(c10, av.y, wA.y);
                fma2(c11, av.x, wB.x); fma2(c11, av.y, wB.y);
                av = a2p[i];
                fma2(c20, av.x, wA.x); fma2(c20, av.y, wA.y);
                fma2(c21, av.x, wB.x); fma2(c21, av.y, wB.y);
                av = a3p[i];
                fma2(c30, av.x, wA.x); fma2(c30, av.y, wA.y);
                fma2(c31, av.x, wB.x); fma2(c31, av.y, wB.y);
            }
        }
        __syncthreads();
        {
            int ib = kc * 256 + jj2 * 2;
            *(ulonglong2*)&sred[ib + (bg2 +  0) * 8] = make_ulonglong2(c00, c01);
            *(ulonglong2*)&sred[ib + (bg2 +  8) * 8] = make_ulonglong2(c10, c11);
            *(ulonglong2*)&sred[ib + (bg2 + 16) * 8] = make_ulonglong2(c20, c21);
            *(ulonglong2*)&sred[ib + (bg2 + 24) * 8] = make_ulonglong2(c30, c31);
        }
        __syncthreads();
        if (tid < 256) {
            ull s = sred[tid];
#pragma unroll
            for (int p = 1; p < 16; p++) add2(s, sred[p * 256 + tid]);
            float c  = tanhf(xc_pf + hadd2(s));
            float hn = u_pf * ho_pf + (1.f - u_pf) * c;
            __stcg(&g_h[e2b * PITCH + jc0 + e2j], hn);
            y[(size_t)m2 * Uz + jc0 + e2j] = hn;
        }
        nb++; gsync(base + nb * NBLK);
    }

    for (int i = blk * NTHR + tid; i < Bz * Uz; i += NBLK * NTHR) {
        int b = i >> 10, u = i & 1023;
        s_out[i] = __ldcg(&g_h[b * PITCH + u]);
    }
}

// ------------------------------------------------------------------
extern "C" void kernel_launch(void* const* d_in, const int* in_sizes, int n_in,
                              void* d_out, int out_size)
{
    const int*   x    = (const int*)  d_in[0];
    const float* h0_0 = (const float*)d_in[1];
    const float* h0_1 = (const float*)d_in[2];
    const float* emb  = (const float*)d_in[3];
    const float* Wg0  = (const float*)d_in[4];
    const float* bg0  = (const float*)d_in[5];
    const float* Wc0  = (const float*)d_in[6];
    const float* bc0  = (const float*)d_in[7];
    const float* Wg1  = (const float*)d_in[8];
    const float* bg1  = (const float*)d_in[9];
    const float* Wc1  = (const float*)d_in[10];
    const float* bc1  = (const float*)d_in[11];
    float* out = (float*)d_out;

    float *Xg, *Xc, *y0;
    cudaGetSymbolAddress((void**)&Xg, g_Xg);
    cudaGetSymbolAddress((void**)&Xc, g_Xc);
    cudaGetSymbolAddress((void**)&y0, g_y0);

    static int smem_set = 0;
    if (!smem_set) {
        cudaFuncSetAttribute(gru_scan, cudaFuncAttributeMaxDynamicSharedMemorySize, SMEM_BYTES);
        smem_set = 1;
    }

    float* s0_out = out + (size_t)BSz * Uz;
    float* s1_out = s0_out + Bz * Uz;

    // ---------- layer 0 ----------
    sgemm_bias<<<dim3(U2 / 128, BSz / 128), 256>>>(emb, x, Wg0, bg0, Xg, BSz, U2, Ez);
    sgemm_bias<<<dim3(Uz / 128, BSz / 128), 256>>>(emb, x, Wc0, bc0, Xc, BSz, Uz, Ez);
    set_base<<<1, 1>>>();
    gru_scan<<<NBLK, NTHR, SMEM_BYTES>>>(
        Wg0 + (size_t)Ez * U2, Wc0 + (size_t)Ez * Uz, Xg, Xc, h0_0, y0, s0_out);

    // ---------- layer 1 ----------
    sgemm_bias<<<dim3(U2 / 128, BSz / 128), 256>>>(y0, nullptr, Wg1, bg1, Xg, BSz, U2, Uz);
    sgemm_bias<<<dim3(Uz / 128, BSz / 128), 256>>>(y0, nullptr, Wc1, bc1, Xc, BSz, Uz, Uz);
    set_base<<<1, 1>>>();
    gru_scan<<<NBLK, NTHR, SMEM_BYTES>>>(
        Wg1 + (size_t)Uz * U2, Wc1 + (size_t)Uz * Uz, Xg, Xc, h0_1, out, s1_out);
}